// round 6
// baseline (speedup 1.0000x reference)
#include <cuda_runtime.h>
#include <cuda_fp16.h>
#include <string.h>

// GooLayer: B=2, M=64, D=64, T=8192 — chunked linear-scan, 4 kernels:
//  K0: homogeneous M^CL columns per (m,d)      (shared across b and chunks)
//  K1: pass A — zero-IC particular finals per (bm,chunk,d); stores g=f+ki*h as fp16
//  K2: combine — 16 sequential 2x2 matvecs per chain -> true chunk ICs
//  K3: pass B — re-run each chunk from its IC using fp16 g; tanh + reduce -> out
// Pass A integrates with the fp16-ROUNDED g, so K3's recurrence is exactly
// consistent with the combine chain; the only new error is g rounding (~5e-4 rel).

#define BBX 2
#define MMX 64
#define DDX 64
#define TTX 8192
#define DAMP 0.9998f
#define NCH 16
#define CL (TTX / NCH)                  // 512
#define L2E2 2.8853900817779268f        // 2*log2(e)

__device__ uint4 g_scr[(size_t)BBX * MMX * DDX * TTX / 8];  // fp16 g, 8/uint4 (134MB bss)
__device__ float g_fin[BBX * MMX * NCH * DDX * 2];
__device__ float g_ic [BBX * MMX * NCH * DDX * 2];
__device__ float g_hom[MMX * DDX * 4];

__device__ __forceinline__ float ex2_fast(float x) {
    float y; asm("ex2.approx.f32 %0, %1;" : "=f"(y) : "f"(x)); return y;
}
__device__ __forceinline__ float rcp_fast(float x) {
    float y; asm("rcp.approx.f32 %0, %1;" : "=f"(y) : "f"(x)); return y;
}

// ---------------- K0: homogeneous M^CL per (m,d) ----------------
__global__ __launch_bounds__(256)
void k0_homog(const float* __restrict__ masses, const float* __restrict__ tensions)
{
    int idx = blockIdx.x * 256 + threadIdx.x;      // 0..4095 = m*64+d
    int m = idx >> 6;
    float nki = -(tensions[idx] / masses[m]);
    float p1 = 1.f, v1 = 0.f, p2 = 0.f, v2 = 1.f;
    #pragma unroll 8
    for (int t = 0; t < CL; t++) {
        v1 = fmaf(v1, DAMP, nki * p1); p1 = fmaf(v1, DAMP, p1);
        v2 = fmaf(v2, DAMP, nki * p2); p2 = fmaf(v2, DAMP, p2);
    }
    ((float4*)g_hom)[idx] = make_float4(p1, v1, p2, v2);
}

// ---------------- K1: pass A (particular finals + fp16 g store) ----------------
__global__ __launch_bounds__(256)
void k1_passA(const float* __restrict__ forces, const float* __restrict__ home,
              const float* __restrict__ masses, const float* __restrict__ tensions)
{
    const int tid = threadIdx.x, wid = tid >> 5, lane = tid & 31;
    const int gid   = blockIdx.x * 8 + wid;        // 0..4095
    const int bm    = gid >> 5;                    // 0..127
    const int chunk = (gid >> 1) & 15;
    const int half  = gid & 1;
    const int m = bm & 63;
    const int d = half * 32 + lane;

    const float ki  = tensions[m * 64 + d] / masses[m];
    const float nki = -ki;

    const size_t base = ((size_t)(bm * 64 + d)) * TTX + (size_t)chunk * CL;
    const float4* __restrict__ f4p = (const float4*)(forces + base);
    const float4* __restrict__ h4p = (const float4*)(home + base);
    uint4* gw = g_scr + (base >> 3);

    float pos = 0.f, vs = 0.f;
    float4 fb[2][2], hb[2][2];
    fb[0][0] = __ldcs(f4p + 0); fb[0][1] = __ldcs(f4p + 1);
    hb[0][0] = __ldcs(h4p + 0); hb[0][1] = __ldcs(h4p + 1);

    const int NWND = CL / 8;                       // 64 windows of 8 steps
    for (int w = 0; w < NWND; w++) {
        const int cur = w & 1, nxt = cur ^ 1;
        if (w + 1 < NWND) {
            fb[nxt][0] = __ldcs(f4p + 2 * (w + 1));     fb[nxt][1] = __ldcs(f4p + 2 * (w + 1) + 1);
            hb[nxt][0] = __ldcs(h4p + 2 * (w + 1));     hb[nxt][1] = __ldcs(h4p + 2 * (w + 1) + 1);
        }
        float g[8];
        #pragma unroll
        for (int i = 0; i < 2; i++)
            #pragma unroll
            for (int k = 0; k < 4; k++)
                g[i * 4 + k] = fmaf(ki, (&hb[cur][i].x)[k], (&fb[cur][i].x)[k]);

        // round to fp16 (store) and integrate with the ROUNDED values
        uint4 pk; float gf[8];
        #pragma unroll
        for (int i = 0; i < 4; i++) {
            __half2 h2 = __floats2half2_rn(g[2 * i], g[2 * i + 1]);
            unsigned u; memcpy(&u, &h2, 4);
            (&pk.x)[i] = u;
            float2 f2 = __half22float2(h2);
            gf[2 * i] = f2.x; gf[2 * i + 1] = f2.y;
        }
        __stcs(gw + w, pk);

        #pragma unroll
        for (int s = 0; s < 8; s++) {
            float acc = fmaf(nki, pos, gf[s]);
            vs  = fmaf(vs, DAMP, acc);
            pos = fmaf(vs, DAMP, pos);
        }
    }
    float* fin = g_fin + ((size_t)(bm * NCH + chunk) * 64 + d) * 2;
    fin[0] = pos; fin[1] = vs;
}

// ---------------- K2: combine (chunk ICs) ----------------
__global__ __launch_bounds__(256)
void k2_combine()
{
    int idx = blockIdx.x * 256 + threadIdx.x;      // 0..8191 = bm*64+d
    int bm = idx >> 6, d = idx & 63, m = bm & 63;
    float4 A = ((const float4*)g_hom)[m * 64 + d]; // {A00,A10,A01,A11}
    float pos = 0.f, vs = 0.f;
    #pragma unroll
    for (int c = 0; c < NCH; c++) {
        size_t o = ((size_t)(bm * NCH + c) * 64 + d) * 2;
        g_ic[o] = pos; g_ic[o + 1] = vs;
        float np = fmaf(A.x, pos, fmaf(A.z, vs, g_fin[o]));
        float nv = fmaf(A.y, pos, fmaf(A.w, vs, g_fin[o + 1]));
        pos = np; vs = nv;
    }
}

// ---------------- K3: pass B (recurrence + tanh + reduce -> out) ----------------
__global__ __launch_bounds__(256)
void k3_passB(const float* __restrict__ mic, const float* __restrict__ masses,
              const float* __restrict__ tensions, const float* __restrict__ gains,
              float* __restrict__ out)
{
    __shared__ float tile_s[8][16][36];
    __shared__ float xbuf[4][2][16];

    const int tid = threadIdx.x, wid = tid >> 5, lane = tid & 31;
    const int u = wid >> 1, half = wid & 1;
    const int bm = blockIdx.x >> 2, cg = blockIdx.x & 3;
    const int chunk = cg * 4 + u;
    const int m = bm & 63, d = half * 32 + lane;

    const float ki    = tensions[m * 64 + d] / masses[m];
    const float nki   = -ki;
    const float karg  = gains[m] * (DAMP * L2E2);
    const float micv  = mic[bm * 64 + d];
    const float m2mic = -2.f * micv;

    const size_t base = ((size_t)(bm * 64 + d)) * TTX + (size_t)chunk * CL;
    const uint4* gw = g_scr + (base >> 3);
    const size_t io = ((size_t)(bm * NCH + chunk) * 64 + d) * 2;
    float pos = g_ic[io], vs = g_ic[io + 1];
    float* obase = out + (size_t)bm * TTX + (size_t)chunk * CL;
    float (*tile)[36] = tile_s[wid];

    uint4 gb[2][2];
    gb[0][0] = __ldcs(gw + 0); gb[0][1] = __ldcs(gw + 1);

    const int NWND = CL / 16;                      // 32 windows of 16 steps
    for (int w = 0; w < NWND; w++) {
        const int cur = w & 1, nxt = cur ^ 1;
        if (w + 1 < NWND) {
            gb[nxt][0] = __ldcs(gw + 2 * (w + 1));
            gb[nxt][1] = __ldcs(gw + 2 * (w + 1) + 1);
        }
        #pragma unroll
        for (int q = 0; q < 2; q++) {
            #pragma unroll
            for (int i = 0; i < 4; i++) {
                unsigned uu = (&gb[cur][q].x)[i];
                __half2 h2; memcpy(&h2, &uu, 4);
                float2 f2 = __half22float2(h2);
                #pragma unroll
                for (int s = 0; s < 2; s++) {
                    float gv  = s ? f2.y : f2.x;
                    float acc = fmaf(nki, pos, gv);
                    vs  = fmaf(vs, DAMP, acc);
                    pos = fmaf(vs, DAMP, pos);
                    float e = ex2_fast(vs * karg);
                    float r = rcp_fast(e + 1.f);
                    tile[q * 8 + i * 2 + s][lane] = fmaf(r, m2mic, micv);
                }
            }
        }
        __syncwarp();

        // transpose reduce: lanes 0-15 sum cols 0-15 of row lane&15, lanes 16-31
        // sum cols 16-31; shfl folds the two 16-col partials.
        const int row = lane & 15, cb = (lane >> 4) * 16;
        float s0 = 0.f, s1 = 0.f, s2 = 0.f, s3 = 0.f;
        #pragma unroll
        for (int i = 0; i < 4; i++) {
            float4 v = *(const float4*)&tile[row][cb + 4 * i];
            s0 += v.x; s1 += v.y; s2 += v.z; s3 += v.w;
        }
        float sum = (s0 + s1) + (s2 + s3);
        sum += __shfl_down_sync(0xffffffffu, sum, 16);

        if (half == 0) {
            if (lane < 16) xbuf[u][cur][lane] = sum;
            asm volatile("bar.sync %0, 64;" :: "r"(u + 1) : "memory");
        } else {
            asm volatile("bar.sync %0, 64;" :: "r"(u + 1) : "memory");
            if (lane < 16) obase[w * 16 + lane] = sum + xbuf[u][cur][lane];
        }
        __syncwarp();
    }
}

extern "C" void kernel_launch(void* const* d_in, const int* in_sizes, int n_in,
                              void* d_out, int out_size)
{
    const float* forces   = (const float*)d_in[0];
    const float* home     = (const float*)d_in[1];
    const float* mic      = (const float*)d_in[2];
    const float* masses   = (const float*)d_in[3];
    const float* tensions = (const float*)d_in[4];
    const float* gains    = (const float*)d_in[5];

    k0_homog  <<<16,  256>>>(masses, tensions);
    k1_passA  <<<512, 256>>>(forces, home, masses, tensions);
    k2_combine<<<32,  256>>>();
    k3_passB  <<<512, 256>>>(mic, masses, tensions, gains, (float*)d_out);
}

// round 8
// speedup vs baseline: 1.0913x; 1.0913x over previous
#include <cuda_runtime.h>
#include <cuda_fp16.h>
#include <string.h>

// GooLayer: B=2, M=64, D=64, T=8192 — chunked linear-scan, 4 kernels:
//  K0: homogeneous M^CL columns per (m,d)
//  K1: pass A — particular finals per (bm,chunk,d); stores g=f+ki*h as fp16
//      with first-order noise-shaped rounding (error feedback), and integrates
//      the ROUNDED values so K2/K3 are exactly consistent.
//  K2: combine — 16 sequential 2x2 matvecs per chain -> true chunk ICs
//  K3: pass B — re-run each chunk from its IC on fp16 g; tanh + reduce -> out
// All double buffers are NAMED variables (no runtime-indexed register arrays
// -> no local-memory spills).

#define BBX 2
#define MMX 64
#define DDX 64
#define TTX 8192
#define DAMP 0.9998f
#define NCH 16
#define CL (TTX / NCH)                  // 512
#define L2E2 2.8853900817779268f        // 2*log2(e)

__device__ uint4 g_scr[(size_t)BBX * MMX * DDX * TTX / 8];  // fp16 g
__device__ float g_fin[BBX * MMX * NCH * DDX * 2];
__device__ float g_ic [BBX * MMX * NCH * DDX * 2];
__device__ float g_hom[MMX * DDX * 4];

__device__ __forceinline__ float ex2_fast(float x) {
    float y; asm("ex2.approx.f32 %0, %1;" : "=f"(y) : "f"(x)); return y;
}
__device__ __forceinline__ float rcp_fast(float x) {
    float y; asm("rcp.approx.f32 %0, %1;" : "=f"(y) : "f"(x)); return y;
}
// bit-reinterpret a packed u32 (two fp16) as __half2
__device__ __forceinline__ __half2 u32_as_half2(unsigned u) {
    __half2 h; memcpy(&h, &u, 4); return h;
}

// ---------------- K0: homogeneous M^CL per (m,d) ----------------
__global__ __launch_bounds__(256)
void k0_homog(const float* __restrict__ masses, const float* __restrict__ tensions)
{
    int idx = blockIdx.x * 256 + threadIdx.x;      // m*64+d
    int m = idx >> 6;
    float nki = -(tensions[idx] / masses[m]);
    float p1 = 1.f, v1 = 0.f, p2 = 0.f, v2 = 1.f;
    #pragma unroll 8
    for (int t = 0; t < CL; t++) {
        v1 = fmaf(v1, DAMP, nki * p1); p1 = fmaf(v1, DAMP, p1);
        v2 = fmaf(v2, DAMP, nki * p2); p2 = fmaf(v2, DAMP, p2);
    }
    ((float4*)g_hom)[idx] = make_float4(p1, v1, p2, v2);
}

// quantize 4 g's with noise-shaped error feedback; returns back-converted floats
__device__ __forceinline__ void quant4(float4 fv, float4 hv, float ki, float& e,
                                       float* gf, unsigned short* hq)
{
    #pragma unroll
    for (int k = 0; k < 4; k++) {
        float g = fmaf(ki, (&hv.x)[k], (&fv.x)[k]);
        float t = g + e;
        __half q = __float2half_rn(t);
        float gfv = __half2float(q);
        e = t - gfv;
        gf[k] = gfv;
        hq[k] = __half_as_ushort(q);
    }
}

// ---------------- K1: pass A ----------------
__global__ __launch_bounds__(256)
void k1_passA(const float* __restrict__ forces, const float* __restrict__ home,
              const float* __restrict__ masses, const float* __restrict__ tensions)
{
    const int tid = threadIdx.x, wid = tid >> 5, lane = tid & 31;
    const int gid   = blockIdx.x * 8 + wid;        // 0..4095
    const int bm    = gid >> 5;
    const int chunk = (gid >> 1) & 15;
    const int half  = gid & 1;
    const int m = bm & 63;
    const int d = half * 32 + lane;

    const float ki  = tensions[m * 64 + d] / masses[m];
    const float nki = -ki;

    const size_t base = ((size_t)(bm * 64 + d)) * TTX + (size_t)chunk * CL;
    const float4* __restrict__ f4p = (const float4*)(forces + base);
    const float4* __restrict__ h4p = (const float4*)(home + base);
    uint4* gw = g_scr + (base >> 3);               // 1 uint4 per 8-step window

    float pos = 0.f, vs = 0.f, e = 0.f;

    float4 fa0, fa1, ha0, ha1, fb0, fb1, hb0, hb1;
    fa0 = __ldcs(f4p + 0); fa1 = __ldcs(f4p + 1);
    ha0 = __ldcs(h4p + 0); ha1 = __ldcs(h4p + 1);

    const int NWND = CL / 8;                       // 64 windows of 8 steps

#define K1W(W, CF0, CF1, CH0, CH1, NF0, NF1, NH0, NH1)                         \
    {                                                                          \
        const int w_ = (W);                                                    \
        if (w_ + 1 < NWND) {                                                   \
            NF0 = __ldcs(f4p + 2 * (w_ + 1));                                  \
            NF1 = __ldcs(f4p + 2 * (w_ + 1) + 1);                              \
            NH0 = __ldcs(h4p + 2 * (w_ + 1));                                  \
            NH1 = __ldcs(h4p + 2 * (w_ + 1) + 1);                              \
        }                                                                      \
        float gf[8]; unsigned short hq[8];                                     \
        quant4(CF0, CH0, ki, e, gf + 0, hq + 0);                               \
        quant4(CF1, CH1, ki, e, gf + 4, hq + 4);                               \
        uint4 pk;                                                              \
        pk.x = (unsigned)hq[0] | ((unsigned)hq[1] << 16);                      \
        pk.y = (unsigned)hq[2] | ((unsigned)hq[3] << 16);                      \
        pk.z = (unsigned)hq[4] | ((unsigned)hq[5] << 16);                      \
        pk.w = (unsigned)hq[6] | ((unsigned)hq[7] << 16);                      \
        __stcs(gw + w_, pk);                                                   \
        _Pragma("unroll")                                                      \
        for (int s = 0; s < 8; s++) {                                          \
            float acc = fmaf(nki, pos, gf[s]);                                 \
            vs  = fmaf(vs, DAMP, acc);                                         \
            pos = fmaf(vs, DAMP, pos);                                         \
        }                                                                      \
    }

    for (int w = 0; w < NWND; w += 2) {
        K1W(w,     fa0, fa1, ha0, ha1, fb0, fb1, hb0, hb1)
        K1W(w + 1, fb0, fb1, hb0, hb1, fa0, fa1, ha0, ha1)
    }
#undef K1W

    float* fin = g_fin + ((size_t)(bm * NCH + chunk) * 64 + d) * 2;
    fin[0] = pos; fin[1] = vs;
}

// ---------------- K2: combine (chunk ICs) ----------------
__global__ __launch_bounds__(256)
void k2_combine()
{
    int idx = blockIdx.x * 256 + threadIdx.x;      // bm*64+d
    int bm = idx >> 6, d = idx & 63, m = bm & 63;
    float4 A = ((const float4*)g_hom)[m * 64 + d]; // {A00,A10,A01,A11}
    float pos = 0.f, vs = 0.f;
    #pragma unroll
    for (int c = 0; c < NCH; c++) {
        size_t o = ((size_t)(bm * NCH + c) * 64 + d) * 2;
        g_ic[o] = pos; g_ic[o + 1] = vs;
        float np = fmaf(A.x, pos, fmaf(A.z, vs, g_fin[o]));
        float nv = fmaf(A.y, pos, fmaf(A.w, vs, g_fin[o + 1]));
        pos = np; vs = nv;
    }
}

// ---------------- K3: pass B ----------------
__global__ __launch_bounds__(256)
void k3_passB(const float* __restrict__ mic, const float* __restrict__ masses,
              const float* __restrict__ tensions, const float* __restrict__ gains,
              float* __restrict__ out)
{
    __shared__ float tile_s[8][16][36];
    __shared__ float xbuf[4][2][16];

    const int tid = threadIdx.x, wid = tid >> 5, lane = tid & 31;
    const int u = wid >> 1, half = wid & 1;
    const int bm = blockIdx.x >> 2, cg = blockIdx.x & 3;
    const int chunk = cg * 4 + u;
    const int m = bm & 63, d = half * 32 + lane;

    const float ki    = tensions[m * 64 + d] / masses[m];
    const float nki   = -ki;
    const float karg  = gains[m] * (DAMP * L2E2);
    const float micv  = mic[bm * 64 + d];
    const float m2mic = -2.f * micv;

    const size_t base = ((size_t)(bm * 64 + d)) * TTX + (size_t)chunk * CL;
    const uint4* gw = g_scr + (base >> 3);
    const size_t io = ((size_t)(bm * NCH + chunk) * 64 + d) * 2;
    float pos = g_ic[io], vs = g_ic[io + 1];
    float* obase = out + (size_t)bm * TTX + (size_t)chunk * CL;
    float (*tile)[36] = tile_s[wid];

    uint4 ga0, ga1, gb0, gb1;
    ga0 = __ldcs(gw + 0); ga1 = __ldcs(gw + 1);

    const int NWND = CL / 16;                      // 32 windows of 16 steps

    // process one uint4 (8 fp16 g's) starting at tile row R
#define K3_Q(GQ, R)                                                            \
    _Pragma("unroll")                                                          \
    for (int i = 0; i < 4; i++) {                                              \
        float2 f2 = __half22float2(u32_as_half2((&GQ.x)[i]));                  \
        _Pragma("unroll")                                                      \
        for (int s = 0; s < 2; s++) {                                          \
            float gv  = s ? f2.y : f2.x;                                       \
            float acc = fmaf(nki, pos, gv);                                    \
            vs  = fmaf(vs, DAMP, acc);                                         \
            pos = fmaf(vs, DAMP, pos);                                         \
            float ex = ex2_fast(vs * karg);                                    \
            float r  = rcp_fast(ex + 1.f);                                     \
            tile[(R) + i * 2 + s][lane] = fmaf(r, m2mic, micv);                \
        }                                                                      \
    }

#define K3W(W, C0, C1, N0, N1)                                                 \
    {                                                                          \
        const int w_ = (W);                                                    \
        if (w_ + 1 < NWND) {                                                   \
            N0 = __ldcs(gw + 2 * (w_ + 1));                                    \
            N1 = __ldcs(gw + 2 * (w_ + 1) + 1);                                \
        }                                                                      \
        K3_Q(C0, 0)                                                            \
        K3_Q(C1, 8)                                                            \
        __syncwarp();                                                          \
        const int row = lane & 15, cb = (lane >> 4) * 16;                      \
        float s0 = 0.f, s1 = 0.f, s2 = 0.f, s3 = 0.f;                          \
        _Pragma("unroll")                                                      \
        for (int i = 0; i < 4; i++) {                                          \
            float4 v = *(const float4*)&tile[row][cb + 4 * i];                 \
            s0 += v.x; s1 += v.y; s2 += v.z; s3 += v.w;                        \
        }                                                                      \
        float sum = (s0 + s1) + (s2 + s3);                                     \
        sum += __shfl_down_sync(0xffffffffu, sum, 16);                         \
        if (half == 0) {                                                       \
            if (lane < 16) xbuf[u][w_ & 1][lane] = sum;                        \
            asm volatile("bar.sync %0, 64;" :: "r"(u + 1) : "memory");         \
        } else {                                                               \
            asm volatile("bar.sync %0, 64;" :: "r"(u + 1) : "memory");         \
            if (lane < 16) obase[w_ * 16 + lane] = sum + xbuf[u][w_ & 1][lane];\
        }                                                                      \
        __syncwarp();                                                          \
    }

    for (int w = 0; w < NWND; w += 2) {
        K3W(w,     ga0, ga1, gb0, gb1)
        K3W(w + 1, gb0, gb1, ga0, ga1)
    }
#undef K3W
#undef K3_Q
}

extern "C" void kernel_launch(void* const* d_in, const int* in_sizes, int n_in,
                              void* d_out, int out_size)
{
    const float* forces   = (const float*)d_in[0];
    const float* home     = (const float*)d_in[1];
    const float* mic      = (const float*)d_in[2];
    const float* masses   = (const float*)d_in[3];
    const float* tensions = (const float*)d_in[4];
    const float* gains    = (const float*)d_in[5];

    k0_homog  <<<16,  256>>>(masses, tensions);
    k1_passA  <<<512, 256>>>(forces, home, masses, tensions);
    k2_combine<<<32,  256>>>();
    k3_passB  <<<512, 256>>>(mic, masses, tensions, gains, (float*)d_out);
}

// round 9
// speedup vs baseline: 1.3812x; 1.2657x over previous
#include <cuda_runtime.h>
#include <cuda_fp16.h>
#include <string.h>

// GooLayer: B=2, M=64, D=64, T=8192 — chunked linear-scan, 4 kernels:
//  K0: homogeneous M^CL columns per (m,d)
//  K1: pass A — particular finals per (bm,chunk,d); stores g=f+ki*h as fp16
//      (noise-shaped rounding) in a d-major layout; COALESCED f/h loads via
//      smem transpose staging, coalesced g stores.
//  K2: combine — 16 sequential 2x2 matvecs per chain -> true chunk ICs
//  K3: pass B — re-run chunk from IC on fp16 g (coalesced loads); tanh+reduce.

#define BBX 2
#define MMX 64
#define DDX 64
#define TTX 8192
#define DAMP 0.9998f
#define NCH 16
#define CL (TTX / NCH)                  // 512
#define NW8 (CL / 8)                    // 64  fp16-octet windows per chunk
#define NTILE (CL / 16)                 // 32  16-step tiles per chunk
#define FQ (TTX / 4)                    // float4 per chain
#define L2E2 2.8853900817779268f        // 2*log2(e)

// g scratch: [bm][chunk][w8][d] -> uint4 (8 fp16), coalesced in d
__device__ uint4 g_scr[(size_t)BBX * MMX * NCH * NW8 * DDX];
__device__ float g_fin[BBX * MMX * NCH * DDX * 2];
__device__ float g_ic [BBX * MMX * NCH * DDX * 2];
__device__ float g_hom[MMX * DDX * 4];

__device__ __forceinline__ float ex2_fast(float x) {
    float y; asm("ex2.approx.f32 %0, %1;" : "=f"(y) : "f"(x)); return y;
}
__device__ __forceinline__ float rcp_fast(float x) {
    float y; asm("rcp.approx.f32 %0, %1;" : "=f"(y) : "f"(x)); return y;
}
__device__ __forceinline__ __half2 u32_as_half2(unsigned u) {
    __half2 h; memcpy(&h, &u, 4); return h;
}

// ---------------- K0: homogeneous M^CL per (m,d) ----------------
__global__ __launch_bounds__(256)
void k0_homog(const float* __restrict__ masses, const float* __restrict__ tensions)
{
    int idx = blockIdx.x * 256 + threadIdx.x;      // m*64+d
    int m = idx >> 6;
    float nki = -(tensions[idx] / masses[m]);
    float p1 = 1.f, v1 = 0.f, p2 = 0.f, v2 = 1.f;
    #pragma unroll 8
    for (int t = 0; t < CL; t++) {
        v1 = fmaf(v1, DAMP, nki * p1); p1 = fmaf(v1, DAMP, p1);
        v2 = fmaf(v2, DAMP, nki * p2); p2 = fmaf(v2, DAMP, p2);
    }
    ((float4*)g_hom)[idx] = make_float4(p1, v1, p2, v2);
}

// ---------------- K1: pass A (coalesced via smem transpose) ----------------
__global__ __launch_bounds__(256)
void k1_passA(const float* __restrict__ forces, const float* __restrict__ home,
              const float* __restrict__ masses, const float* __restrict__ tensions)
{
    // per-warp transpose tiles: 32 chains x 16 t, row stride 20 floats (80B)
    __shared__ float ft[8][32][20];
    __shared__ float ht[8][32][20];

    const int tid = threadIdx.x, wid = tid >> 5, lane = tid & 31;
    const int gid   = blockIdx.x * 8 + wid;        // 0..4095
    const int bm    = gid >> 5;
    const int chunk = (gid >> 1) & 15;
    const int half  = gid & 1;
    const int m = bm & 63;
    const int d = half * 32 + lane;

    const float ki  = tensions[m * 64 + d] / masses[m];
    const float nki = -ki;

    // load mapping: per LDG.128, lanes cover 4 chains x 4 float4 of t
    const int lch = lane >> 2;                     // 0..7
    const int ltf = lane & 3;                      // 0..3
    const size_t wbase = ((size_t)(bm * 64 + half * 32)) * TTX + (size_t)chunk * CL;
    const float4* fld = (const float4*)(forces + wbase) + (size_t)lch * FQ + ltf;
    const float4* hld = (const float4*)(home  + wbase) + (size_t)lch * FQ + ltf;

    uint4* gw = g_scr + ((size_t)(bm * NCH + chunk) * NW8) * 64 + d;

    float pos = 0.f, vs = 0.f, e = 0.f;

    float4 nf0, nf1, nf2, nf3, nh0, nh1, nh2, nh3;
    nf0 = __ldcs(fld + 0 * 8 * FQ); nf1 = __ldcs(fld + 1 * 8 * FQ);
    nf2 = __ldcs(fld + 2 * 8 * FQ); nf3 = __ldcs(fld + 3 * 8 * FQ);
    nh0 = __ldcs(hld + 0 * 8 * FQ); nh1 = __ldcs(hld + 1 * 8 * FQ);
    nh2 = __ldcs(hld + 2 * 8 * FQ); nh3 = __ldcs(hld + 3 * 8 * FQ);

    for (int tile = 0; tile < NTILE; tile++) {
        __syncwarp();
        *(float4*)&ft[wid][ 0 + lch][ltf * 4] = nf0;
        *(float4*)&ft[wid][ 8 + lch][ltf * 4] = nf1;
        *(float4*)&ft[wid][16 + lch][ltf * 4] = nf2;
        *(float4*)&ft[wid][24 + lch][ltf * 4] = nf3;
        *(float4*)&ht[wid][ 0 + lch][ltf * 4] = nh0;
        *(float4*)&ht[wid][ 8 + lch][ltf * 4] = nh1;
        *(float4*)&ht[wid][16 + lch][ltf * 4] = nh2;
        *(float4*)&ht[wid][24 + lch][ltf * 4] = nh3;
        __syncwarp();

        // prefetch next tile into registers (hides DRAM behind compute)
        if (tile + 1 < NTILE) {
            const int o = (tile + 1) * 4;
            nf0 = __ldcs(fld + 0 * 8 * FQ + o); nf1 = __ldcs(fld + 1 * 8 * FQ + o);
            nf2 = __ldcs(fld + 2 * 8 * FQ + o); nf3 = __ldcs(fld + 3 * 8 * FQ + o);
            nh0 = __ldcs(hld + 0 * 8 * FQ + o); nh1 = __ldcs(hld + 1 * 8 * FQ + o);
            nh2 = __ldcs(hld + 2 * 8 * FQ + o); nh3 = __ldcs(hld + 3 * 8 * FQ + o);
        }

        // compute 16 steps for chain = lane; quantize g with error feedback
        unsigned hq2[8];   // 8 packed half2 (constant-indexed, fully unrolled)
        #pragma unroll
        for (int j = 0; j < 4; j++) {
            float4 fv = *(const float4*)&ft[wid][lane][4 * j];
            float4 hv = *(const float4*)&ht[wid][lane][4 * j];
            #pragma unroll
            for (int p = 0; p < 2; p++) {
                float g0 = fmaf(ki, (&hv.x)[2 * p],     (&fv.x)[2 * p]);
                float t0 = g0 + e;
                __half q0 = __float2half_rn(t0);
                float r0 = __half2float(q0);
                e = t0 - r0;
                float acc0 = fmaf(nki, pos, r0);
                vs  = fmaf(vs, DAMP, acc0);
                pos = fmaf(vs, DAMP, pos);

                float g1 = fmaf(ki, (&hv.x)[2 * p + 1], (&fv.x)[2 * p + 1]);
                float t1 = g1 + e;
                __half q1 = __float2half_rn(t1);
                float r1 = __half2float(q1);
                e = t1 - r1;
                float acc1 = fmaf(nki, pos, r1);
                vs  = fmaf(vs, DAMP, acc1);
                pos = fmaf(vs, DAMP, pos);

                hq2[j * 2 + p] = (unsigned)__half_as_ushort(q0)
                               | ((unsigned)__half_as_ushort(q1) << 16);
            }
        }
        uint4 p0, p1;
        p0.x = hq2[0]; p0.y = hq2[1]; p0.z = hq2[2]; p0.w = hq2[3];
        p1.x = hq2[4]; p1.y = hq2[5]; p1.z = hq2[6]; p1.w = hq2[7];
        __stcs(gw + (size_t)(tile * 2 + 0) * 64, p0);   // coalesced in d
        __stcs(gw + (size_t)(tile * 2 + 1) * 64, p1);
    }

    float* fin = g_fin + ((size_t)(bm * NCH + chunk) * 64 + d) * 2;
    fin[0] = pos; fin[1] = vs;
}

// ---------------- K2: combine (chunk ICs) ----------------
__global__ __launch_bounds__(256)
void k2_combine()
{
    int idx = blockIdx.x * 256 + threadIdx.x;      // bm*64+d
    int bm = idx >> 6, d = idx & 63, m = bm & 63;
    float4 A = ((const float4*)g_hom)[m * 64 + d]; // {A00,A10,A01,A11}
    float pos = 0.f, vs = 0.f;
    #pragma unroll
    for (int c = 0; c < NCH; c++) {
        size_t o = ((size_t)(bm * NCH + c) * 64 + d) * 2;
        g_ic[o] = pos; g_ic[o + 1] = vs;
        float np = fmaf(A.x, pos, fmaf(A.z, vs, g_fin[o]));
        float nv = fmaf(A.y, pos, fmaf(A.w, vs, g_fin[o + 1]));
        pos = np; vs = nv;
    }
}

// ---------------- K3: pass B ----------------
__global__ __launch_bounds__(256)
void k3_passB(const float* __restrict__ mic, const float* __restrict__ masses,
              const float* __restrict__ tensions, const float* __restrict__ gains,
              float* __restrict__ out)
{
    __shared__ float tile_s[8][16][36];
    __shared__ float xbuf[4][2][16];

    const int tid = threadIdx.x, wid = tid >> 5, lane = tid & 31;
    const int u = wid >> 1, half = wid & 1;
    const int bm = blockIdx.x >> 2, cg = blockIdx.x & 3;
    const int chunk = cg * 4 + u;
    const int m = bm & 63, d = half * 32 + lane;

    const float ki    = tensions[m * 64 + d] / masses[m];
    const float nki   = -ki;
    const float karg  = gains[m] * (DAMP * L2E2);
    const float micv  = mic[bm * 64 + d];
    const float m2mic = -2.f * micv;

    // coalesced g reads: [bm][chunk][w8][d]
    const uint4* gw = g_scr + ((size_t)(bm * NCH + chunk) * NW8) * 64 + d;
    const size_t io = ((size_t)(bm * NCH + chunk) * 64 + d) * 2;
    float pos = g_ic[io], vs = g_ic[io + 1];
    float* obase = out + (size_t)bm * TTX + (size_t)chunk * CL;
    float (*tile)[36] = tile_s[wid];

    uint4 ga0, ga1, gb0, gb1;
    ga0 = __ldcs(gw + 0);  ga1 = __ldcs(gw + 64);

    const int NWND = CL / 16;                      // 32 windows of 16 steps

#define K3_Q(GQ, R)                                                            \
    _Pragma("unroll")                                                          \
    for (int i = 0; i < 4; i++) {                                              \
        float2 f2 = __half22float2(u32_as_half2((&GQ.x)[i]));                  \
        _Pragma("unroll")                                                      \
        for (int s = 0; s < 2; s++) {                                          \
            float gv  = s ? f2.y : f2.x;                                       \
            float acc = fmaf(nki, pos, gv);                                    \
            vs  = fmaf(vs, DAMP, acc);                                         \
            pos = fmaf(vs, DAMP, pos);                                         \
            float ex = ex2_fast(vs * karg);                                    \
            float r  = rcp_fast(ex + 1.f);                                     \
            tile[(R) + i * 2 + s][lane] = fmaf(r, m2mic, micv);                \
        }                                                                      \
    }

#define K3W(W, C0, C1, N0, N1)                                                 \
    {                                                                          \
        const int w_ = (W);                                                    \
        if (w_ + 1 < NWND) {                                                   \
            N0 = __ldcs(gw + (size_t)(2 * (w_ + 1) + 0) * 64);                 \
            N1 = __ldcs(gw + (size_t)(2 * (w_ + 1) + 1) * 64);                 \
        }                                                                      \
        K3_Q(C0, 0)                                                            \
        K3_Q(C1, 8)                                                            \
        __syncwarp();                                                          \
        const int row = lane & 15, cb = (lane >> 4) * 16;                      \
        float s0 = 0.f, s1 = 0.f, s2 = 0.f, s3 = 0.f;                          \
        _Pragma("unroll")                                                      \
        for (int i = 0; i < 4; i++) {                                          \
            float4 v = *(const float4*)&tile[row][cb + 4 * i];                 \
            s0 += v.x; s1 += v.y; s2 += v.z; s3 += v.w;                        \
        }                                                                      \
        float sum = (s0 + s1) + (s2 + s3);                                     \
        sum += __shfl_down_sync(0xffffffffu, sum, 16);                         \
        if (half == 0) {                                                       \
            if (lane < 16) xbuf[u][w_ & 1][lane] = sum;                        \
            asm volatile("bar.sync %0, 64;" :: "r"(u + 1) : "memory");         \
        } else {                                                               \
            asm volatile("bar.sync %0, 64;" :: "r"(u + 1) : "memory");         \
            if (lane < 16) obase[w_ * 16 + lane] = sum + xbuf[u][w_ & 1][lane];\
        }                                                                      \
        __syncwarp();                                                          \
    }

    for (int w = 0; w < NWND; w += 2) {
        K3W(w,     ga0, ga1, gb0, gb1)
        K3W(w + 1, gb0, gb1, ga0, ga1)
    }
#undef K3W
#undef K3_Q
}

extern "C" void kernel_launch(void* const* d_in, const int* in_sizes, int n_in,
                              void* d_out, int out_size)
{
    const float* forces   = (const float*)d_in[0];
    const float* home     = (const float*)d_in[1];
    const float* mic      = (const float*)d_in[2];
    const float* masses   = (const float*)d_in[3];
    const float* tensions = (const float*)d_in[4];
    const float* gains    = (const float*)d_in[5];

    k0_homog  <<<16,  256>>>(masses, tensions);
    k1_passA  <<<512, 256>>>(forces, home, masses, tensions);
    k2_combine<<<32,  256>>>();
    k3_passB  <<<512, 256>>>(mic, masses, tensions, gains, (float*)d_out);
}

// round 10
// speedup vs baseline: 1.5995x; 1.1581x over previous
#include <cuda_runtime.h>
#include <cuda_fp16.h>
#include <string.h>

// GooLayer: B=2, M=64, D=64, T=8192 — chunked linear-scan, 4 kernels:
//  K0: homogeneous M^CL columns per (m,d)
//  K1: pass A — particular finals per (bm,chunk,d); stores g=f+ki*h as fp16
//      with 4-way interleaved noise-shaped rounding. Full-line coalesced
//      f/h loads (4 chains x 128B per LDG.128) via smem transpose staging.
//  K2: combine — 16 sequential 2x2 matvecs per chain -> true chunk ICs
//  K3: pass B — re-run chunk from IC on fp16 g (coalesced loads); tanh+reduce.

#define BBX 2
#define MMX 64
#define DDX 64
#define TTX 8192
#define DAMP 0.9998f
#define NCH 16
#define CL (TTX / NCH)                  // 512
#define NW8 (CL / 8)                    // 64  fp16-octet windows per chunk
#define K1TILE 32                       // t per staging tile in K1
#define K1NT (CL / K1TILE)              // 16 tiles per chunk
#define FQ (TTX / 4)                    // float4 per chain (2048)
#define L2E2 2.8853900817779268f        // 2*log2(e)

// g scratch: [bm][chunk][w8][d] -> uint4 (8 fp16, t-pairs), coalesced in d
__device__ uint4 g_scr[(size_t)BBX * MMX * NCH * NW8 * DDX];
__device__ float g_fin[BBX * MMX * NCH * DDX * 2];
__device__ float g_ic [BBX * MMX * NCH * DDX * 2];
__device__ float g_hom[MMX * DDX * 4];

__device__ __forceinline__ float ex2_fast(float x) {
    float y; asm("ex2.approx.f32 %0, %1;" : "=f"(y) : "f"(x)); return y;
}
__device__ __forceinline__ float rcp_fast(float x) {
    float y; asm("rcp.approx.f32 %0, %1;" : "=f"(y) : "f"(x)); return y;
}
__device__ __forceinline__ __half2 u32_as_half2(unsigned u) {
    __half2 h; memcpy(&h, &u, 4); return h;
}
__device__ __forceinline__ unsigned half2_as_u32(__half2 h) {
    unsigned u; memcpy(&u, &h, 4); return u;
}

// ---------------- K0: homogeneous M^CL per (m,d) ----------------
__global__ __launch_bounds__(256)
void k0_homog(const float* __restrict__ masses, const float* __restrict__ tensions)
{
    int idx = blockIdx.x * 256 + threadIdx.x;      // m*64+d
    int m = idx >> 6;
    float nki = -(tensions[idx] / masses[m]);
    float p1 = 1.f, v1 = 0.f, p2 = 0.f, v2 = 1.f;
    #pragma unroll 8
    for (int t = 0; t < CL; t++) {
        v1 = fmaf(v1, DAMP, nki * p1); p1 = fmaf(v1, DAMP, p1);
        v2 = fmaf(v2, DAMP, nki * p2); p2 = fmaf(v2, DAMP, p2);
    }
    ((float4*)g_hom)[idx] = make_float4(p1, v1, p2, v2);
}

// ---------------- K1: pass A ----------------
// 128 threads = 4 warps; one warp per (bm, chunk, half) unit. 1024 blocks.
__global__ __launch_bounds__(128)
void k1_passA(const float* __restrict__ forces, const float* __restrict__ home,
              const float* __restrict__ masses, const float* __restrict__ tensions)
{
    __shared__ float ft[4][32][36];   // [warp][chain][t], stride 144B
    __shared__ float ht[4][32][36];

    const int tid = threadIdx.x, wid = tid >> 5, lane = tid & 31;
    const int unit  = blockIdx.x * 4 + wid;        // 0..4095
    const int bm    = unit >> 5;
    const int chunk = (unit >> 1) & 15;
    const int half  = unit & 1;
    const int m = bm & 63;
    const int d = half * 32 + lane;

    const float ki  = tensions[m * 64 + d] / masses[m];
    const float nki = -ki;

    // load mapping: per LDG.128 instr i, lanes cover 4 chains x 8 float4 (full lines)
    const int lch4 = lane >> 3;                    // chain-in-group 0..3
    const int lt8  = lane & 7;                     // float4 idx 0..7 (32 t)
    const size_t wb = ((size_t)(bm * 64 + half * 32)) * TTX + (size_t)chunk * CL;
    const float4* __restrict__ fbase = (const float4*)(forces + wb) + lt8;
    const float4* __restrict__ hbase = (const float4*)(home  + wb) + lt8;

    uint4* gw = g_scr + ((size_t)(bm * NCH + chunk) * NW8) * 64 + d;

    float pos = 0.f, vs = 0.f;
    float e0 = 0.f, e1 = 0.f, e2 = 0.f, e3 = 0.f;  // 4-way interleaved shaping

    float4 nf0, nf1, nf2, nf3, nf4, nf5, nf6, nf7;
    float4 nh0, nh1, nh2, nh3, nh4, nh5, nh6, nh7;

#define K1_LDALL(OFF)                                                          \
    nf0 = __ldcs(fbase + (size_t)(0 * 4 + lch4) * FQ + (OFF));                 \
    nf1 = __ldcs(fbase + (size_t)(1 * 4 + lch4) * FQ + (OFF));                 \
    nf2 = __ldcs(fbase + (size_t)(2 * 4 + lch4) * FQ + (OFF));                 \
    nf3 = __ldcs(fbase + (size_t)(3 * 4 + lch4) * FQ + (OFF));                 \
    nf4 = __ldcs(fbase + (size_t)(4 * 4 + lch4) * FQ + (OFF));                 \
    nf5 = __ldcs(fbase + (size_t)(5 * 4 + lch4) * FQ + (OFF));                 \
    nf6 = __ldcs(fbase + (size_t)(6 * 4 + lch4) * FQ + (OFF));                 \
    nf7 = __ldcs(fbase + (size_t)(7 * 4 + lch4) * FQ + (OFF));                 \
    nh0 = __ldcs(hbase + (size_t)(0 * 4 + lch4) * FQ + (OFF));                 \
    nh1 = __ldcs(hbase + (size_t)(1 * 4 + lch4) * FQ + (OFF));                 \
    nh2 = __ldcs(hbase + (size_t)(2 * 4 + lch4) * FQ + (OFF));                 \
    nh3 = __ldcs(hbase + (size_t)(3 * 4 + lch4) * FQ + (OFF));                 \
    nh4 = __ldcs(hbase + (size_t)(4 * 4 + lch4) * FQ + (OFF));                 \
    nh5 = __ldcs(hbase + (size_t)(5 * 4 + lch4) * FQ + (OFF));                 \
    nh6 = __ldcs(hbase + (size_t)(6 * 4 + lch4) * FQ + (OFF));                 \
    nh7 = __ldcs(hbase + (size_t)(7 * 4 + lch4) * FQ + (OFF));

    K1_LDALL(0)   // prologue: tile 0

    for (int tile = 0; tile < K1NT; tile++) {
        __syncwarp();
        *(float4*)&ft[wid][ 0 + lch4][lt8 * 4] = nf0;
        *(float4*)&ft[wid][ 4 + lch4][lt8 * 4] = nf1;
        *(float4*)&ft[wid][ 8 + lch4][lt8 * 4] = nf2;
        *(float4*)&ft[wid][12 + lch4][lt8 * 4] = nf3;
        *(float4*)&ft[wid][16 + lch4][lt8 * 4] = nf4;
        *(float4*)&ft[wid][20 + lch4][lt8 * 4] = nf5;
        *(float4*)&ft[wid][24 + lch4][lt8 * 4] = nf6;
        *(float4*)&ft[wid][28 + lch4][lt8 * 4] = nf7;
        *(float4*)&ht[wid][ 0 + lch4][lt8 * 4] = nh0;
        *(float4*)&ht[wid][ 4 + lch4][lt8 * 4] = nh1;
        *(float4*)&ht[wid][ 8 + lch4][lt8 * 4] = nh2;
        *(float4*)&ht[wid][12 + lch4][lt8 * 4] = nh3;
        *(float4*)&ht[wid][16 + lch4][lt8 * 4] = nh4;
        *(float4*)&ht[wid][20 + lch4][lt8 * 4] = nh5;
        *(float4*)&ht[wid][24 + lch4][lt8 * 4] = nh6;
        *(float4*)&ht[wid][28 + lch4][lt8 * 4] = nh7;
        __syncwarp();

        if (tile + 1 < K1NT) { K1_LDALL((tile + 1) * 8) }

        // compute 32 steps for chain = lane; quantize with 4-way shaping
        unsigned uq0 = 0, uq1 = 0, uq2 = 0, uq3 = 0;
        #pragma unroll
        for (int j = 0; j < 8; j++) {
            float4 fv = *(const float4*)&ft[wid][lane][4 * j];
            float4 hv = *(const float4*)&ht[wid][lane][4 * j];
            float t0 = fmaf(ki, hv.x, fv.x) + e0;
            float t1 = fmaf(ki, hv.y, fv.y) + e1;
            float t2 = fmaf(ki, hv.z, fv.z) + e2;
            float t3 = fmaf(ki, hv.w, fv.w) + e3;
            __half2 h2a = __floats2half2_rn(t0, t1);   // packed store word
            __half2 h2b = __floats2half2_rn(t2, t3);
            float2 ra = __half22float2(h2a);
            float2 rb = __half22float2(h2b);
            e0 = t0 - ra.x; e1 = t1 - ra.y;
            e2 = t2 - rb.x; e3 = t3 - rb.y;

            float acc;
            acc = fmaf(nki, pos, ra.x); vs = fmaf(vs, DAMP, acc); pos = fmaf(vs, DAMP, pos);
            acc = fmaf(nki, pos, ra.y); vs = fmaf(vs, DAMP, acc); pos = fmaf(vs, DAMP, pos);
            acc = fmaf(nki, pos, rb.x); vs = fmaf(vs, DAMP, acc); pos = fmaf(vs, DAMP, pos);
            acc = fmaf(nki, pos, rb.y); vs = fmaf(vs, DAMP, acc); pos = fmaf(vs, DAMP, pos);

            // collect 2 u32 per j; store uint4 per 2 j's (8 steps)
            if ((j & 1) == 0) { uq0 = half2_as_u32(h2a); uq1 = half2_as_u32(h2b); }
            else {
                uq2 = half2_as_u32(h2a); uq3 = half2_as_u32(h2b);
                uint4 pk; pk.x = uq0; pk.y = uq1; pk.z = uq2; pk.w = uq3;
                __stcs(gw + (size_t)(tile * 4 + (j >> 1)) * 64, pk);
            }
        }
    }
#undef K1_LDALL

    float* fin = g_fin + ((size_t)(bm * NCH + chunk) * 64 + d) * 2;
    fin[0] = pos; fin[1] = vs;
}

// ---------------- K2: combine (chunk ICs) ----------------
__global__ __launch_bounds__(256)
void k2_combine()
{
    int idx = blockIdx.x * 256 + threadIdx.x;      // bm*64+d
    int bm = idx >> 6, d = idx & 63, m = bm & 63;
    float4 A = ((const float4*)g_hom)[m * 64 + d]; // {A00,A10,A01,A11}
    float pos = 0.f, vs = 0.f;
    #pragma unroll
    for (int c = 0; c < NCH; c++) {
        size_t o = ((size_t)(bm * NCH + c) * 64 + d) * 2;
        g_ic[o] = pos; g_ic[o + 1] = vs;
        float np = fmaf(A.x, pos, fmaf(A.z, vs, g_fin[o]));
        float nv = fmaf(A.y, pos, fmaf(A.w, vs, g_fin[o + 1]));
        pos = np; vs = nv;
    }
}

// ---------------- K3: pass B ----------------
__global__ __launch_bounds__(256)
void k3_passB(const float* __restrict__ mic, const float* __restrict__ masses,
              const float* __restrict__ tensions, const float* __restrict__ gains,
              float* __restrict__ out)
{
    __shared__ float tile_s[8][16][36];
    __shared__ float xbuf[4][2][16];

    const int tid = threadIdx.x, wid = tid >> 5, lane = tid & 31;
    const int u = wid >> 1, half = wid & 1;
    const int bm = blockIdx.x >> 2, cg = blockIdx.x & 3;
    const int chunk = cg * 4 + u;
    const int m = bm & 63, d = half * 32 + lane;

    const float ki    = tensions[m * 64 + d] / masses[m];
    const float nki   = -ki;
    const float karg  = gains[m] * (DAMP * L2E2);
    const float micv  = mic[bm * 64 + d];
    const float m2mic = -2.f * micv;

    const uint4* gw = g_scr + ((size_t)(bm * NCH + chunk) * NW8) * 64 + d;
    const size_t io = ((size_t)(bm * NCH + chunk) * 64 + d) * 2;
    float pos = g_ic[io], vs = g_ic[io + 1];
    float* obase = out + (size_t)bm * TTX + (size_t)chunk * CL;
    float (*tile)[36] = tile_s[wid];

    uint4 ga0, ga1, gb0, gb1;
    ga0 = __ldcs(gw + 0);  ga1 = __ldcs(gw + 64);

    const int NWND = CL / 16;                      // 32 windows of 16 steps

#define K3_Q(GQ, R)                                                            \
    _Pragma("unroll")                                                          \
    for (int i = 0; i < 4; i++) {                                              \
        float2 f2 = __half22float2(u32_as_half2((&GQ.x)[i]));                  \
        _Pragma("unroll")                                                      \
        for (int s = 0; s < 2; s++) {                                          \
            float gv  = s ? f2.y : f2.x;                                       \
            float acc = fmaf(nki, pos, gv);                                    \
            vs  = fmaf(vs, DAMP, acc);                                         \
            pos = fmaf(vs, DAMP, pos);                                         \
            float ex = ex2_fast(vs * karg);                                    \
            float r  = rcp_fast(ex + 1.f);                                     \
            tile[(R) + i * 2 + s][lane] = fmaf(r, m2mic, micv);                \
        }                                                                      \
    }

#define K3W(W, C0, C1, N0, N1)                                                 \
    {                                                                          \
        const int w_ = (W);                                                    \
        if (w_ + 1 < NWND) {                                                   \
            N0 = __ldcs(gw + (size_t)(2 * (w_ + 1) + 0) * 64);                 \
            N1 = __ldcs(gw + (size_t)(2 * (w_ + 1) + 1) * 64);                 \
        }                                                                      \
        K3_Q(C0, 0)                                                            \
        K3_Q(C1, 8)                                                            \
        __syncwarp();                                                          \
        const int row = lane & 15, cb = (lane >> 4) * 16;                      \
        float s0 = 0.f, s1 = 0.f, s2 = 0.f, s3 = 0.f;                          \
        _Pragma("unroll")                                                      \
        for (int i = 0; i < 4; i++) {                                          \
            float4 v = *(const float4*)&tile[row][cb + 4 * i];                 \
            s0 += v.x; s1 += v.y; s2 += v.z; s3 += v.w;                        \
        }                                                                      \
        float sum = (s0 + s1) + (s2 + s3);                                     \
        sum += __shfl_down_sync(0xffffffffu, sum, 16);                         \
        if (half == 0) {                                                       \
            if (lane < 16) xbuf[u][w_ & 1][lane] = sum;                        \
            asm volatile("bar.sync %0, 64;" :: "r"(u + 1) : "memory");         \
        } else {                                                               \
            asm volatile("bar.sync %0, 64;" :: "r"(u + 1) : "memory");         \
            if (lane < 16) obase[w_ * 16 + lane] = sum + xbuf[u][w_ & 1][lane];\
        }                                                                      \
        __syncwarp();                                                          \
    }

    for (int w = 0; w < NWND; w += 2) {
        K3W(w,     ga0, ga1, gb0, gb1)
        K3W(w + 1, gb0, gb1, ga0, ga1)
    }
#undef K3W
#undef K3_Q
}

extern "C" void kernel_launch(void* const* d_in, const int* in_sizes, int n_in,
                              void* d_out, int out_size)
{
    const float* forces   = (const float*)d_in[0];
    const float* home     = (const float*)d_in[1];
    const float* mic      = (const float*)d_in[2];
    const float* masses   = (const float*)d_in[3];
    const float* tensions = (const float*)d_in[4];
    const float* gains    = (const float*)d_in[5];

    k0_homog  <<<16,   256>>>(masses, tensions);
    k1_passA  <<<1024, 128>>>(forces, home, masses, tensions);
    k2_combine<<<32,   256>>>();
    k3_passB  <<<512,  256>>>(mic, masses, tensions, gains, (float*)d_out);
}

// round 11
// speedup vs baseline: 1.6711x; 1.0448x over previous
#include <cuda_runtime.h>
#include <cuda_fp16.h>
#include <string.h>

// GooLayer: B=2, M=64, D=64, T=8192 — chunked linear-scan, 3 kernels:
//  K1: pass A — particular finals per (bm,chunk,d); stores g' = (f+ki*h)*karg
//      as fp16 with 1-way noise-shaped rounding (error feedback). Full-line
//      coalesced f/h loads via smem transpose staging. State is karg-scaled.
//  K2: combine — inline homogeneous M^CL + 16 sequential 2x2 matvecs -> ICs
//  K3: pass B — one warp per (bm,chunk) handles ALL 64 d (2 chains/lane);
//      tanh arg is vs directly (scale folded); combined contribution per step.

#define BBX 2
#define MMX 64
#define DDX 64
#define TTX 8192
#define DAMP 0.9998f
#define NCH 16
#define CL (TTX / NCH)                  // 512
#define NW8 (CL / 8)                    // 64 fp16-octet windows per chunk
#define K1NT (CL / 32)                  // 16 staging tiles per chunk
#define FQ (TTX / 4)                    // float4 per chain (2048)
#define L2E2 2.8853900817779268f        // 2*log2(e)

// g scratch: [bm][chunk][w8][d] -> uint4 (8 fp16, t-ascending), coalesced in d
__device__ uint4 g_scr[(size_t)BBX * MMX * NCH * NW8 * DDX];
__device__ float g_fin[BBX * MMX * NCH * DDX * 2];
__device__ float g_ic [BBX * MMX * NCH * DDX * 2];

__device__ __forceinline__ float ex2_fast(float x) {
    float y; asm("ex2.approx.f32 %0, %1;" : "=f"(y) : "f"(x)); return y;
}
__device__ __forceinline__ float rcp_fast(float x) {
    float y; asm("rcp.approx.f32 %0, %1;" : "=f"(y) : "f"(x)); return y;
}
__device__ __forceinline__ __half2 u32_as_half2(unsigned u) {
    __half2 h; memcpy(&h, &u, 4); return h;
}
__device__ __forceinline__ unsigned half2_as_u32(__half2 h) {
    unsigned u; memcpy(&u, &h, 4); return u;
}

// ---------------- K1: pass A ----------------
// 128 threads = 4 warps; one warp per (bm, chunk, half) unit. 1024 blocks.
__global__ __launch_bounds__(128)
void k1_passA(const float* __restrict__ forces, const float* __restrict__ home,
              const float* __restrict__ masses, const float* __restrict__ tensions,
              const float* __restrict__ gains)
{
    __shared__ float ft[4][32][36];   // [warp][chain][t]
    __shared__ float ht[4][32][36];

    const int tid = threadIdx.x, wid = tid >> 5, lane = tid & 31;
    const int unit  = blockIdx.x * 4 + wid;        // 0..4095
    const int bm    = unit >> 5;
    const int chunk = (unit >> 1) & 15;
    const int half  = unit & 1;
    const int m = bm & 63;
    const int d = half * 32 + lane;

    const float ki   = tensions[m * 64 + d] / masses[m];
    const float nki  = -ki;
    const float karg = gains[m] * (DAMP * L2E2);   // state scale

    // per LDG.128: lanes cover 4 chains x 8 float4 (full 128B lines)
    const int lch4 = lane >> 3;                    // 0..3
    const int lt8  = lane & 7;                     // 0..7
    const size_t wb = ((size_t)(bm * 64 + half * 32)) * TTX + (size_t)chunk * CL;
    const float4* __restrict__ fbase = (const float4*)(forces + wb) + lt8;
    const float4* __restrict__ hbase = (const float4*)(home  + wb) + lt8;

    uint4* gw = g_scr + ((size_t)(bm * NCH + chunk) * NW8) * 64 + d;

    float pos = 0.f, vs = 0.f, e = 0.f;            // karg-scaled state; 1-way shaping

    float4 nf0, nf1, nf2, nf3, nf4, nf5, nf6, nf7;
    float4 nh0, nh1, nh2, nh3, nh4, nh5, nh6, nh7;

#define K1_LDALL(OFF)                                                          \
    nf0 = __ldcs(fbase + (size_t)(0 * 4 + lch4) * FQ + (OFF));                 \
    nf1 = __ldcs(fbase + (size_t)(1 * 4 + lch4) * FQ + (OFF));                 \
    nf2 = __ldcs(fbase + (size_t)(2 * 4 + lch4) * FQ + (OFF));                 \
    nf3 = __ldcs(fbase + (size_t)(3 * 4 + lch4) * FQ + (OFF));                 \
    nf4 = __ldcs(fbase + (size_t)(4 * 4 + lch4) * FQ + (OFF));                 \
    nf5 = __ldcs(fbase + (size_t)(5 * 4 + lch4) * FQ + (OFF));                 \
    nf6 = __ldcs(fbase + (size_t)(6 * 4 + lch4) * FQ + (OFF));                 \
    nf7 = __ldcs(fbase + (size_t)(7 * 4 + lch4) * FQ + (OFF));                 \
    nh0 = __ldcs(hbase + (size_t)(0 * 4 + lch4) * FQ + (OFF));                 \
    nh1 = __ldcs(hbase + (size_t)(1 * 4 + lch4) * FQ + (OFF));                 \
    nh2 = __ldcs(hbase + (size_t)(2 * 4 + lch4) * FQ + (OFF));                 \
    nh3 = __ldcs(hbase + (size_t)(3 * 4 + lch4) * FQ + (OFF));                 \
    nh4 = __ldcs(hbase + (size_t)(4 * 4 + lch4) * FQ + (OFF));                 \
    nh5 = __ldcs(hbase + (size_t)(5 * 4 + lch4) * FQ + (OFF));                 \
    nh6 = __ldcs(hbase + (size_t)(6 * 4 + lch4) * FQ + (OFF));                 \
    nh7 = __ldcs(hbase + (size_t)(7 * 4 + lch4) * FQ + (OFF));

    K1_LDALL(0)

    for (int tile = 0; tile < K1NT; tile++) {
        __syncwarp();
        *(float4*)&ft[wid][ 0 + lch4][lt8 * 4] = nf0;
        *(float4*)&ft[wid][ 4 + lch4][lt8 * 4] = nf1;
        *(float4*)&ft[wid][ 8 + lch4][lt8 * 4] = nf2;
        *(float4*)&ft[wid][12 + lch4][lt8 * 4] = nf3;
        *(float4*)&ft[wid][16 + lch4][lt8 * 4] = nf4;
        *(float4*)&ft[wid][20 + lch4][lt8 * 4] = nf5;
        *(float4*)&ft[wid][24 + lch4][lt8 * 4] = nf6;
        *(float4*)&ft[wid][28 + lch4][lt8 * 4] = nf7;
        *(float4*)&ht[wid][ 0 + lch4][lt8 * 4] = nh0;
        *(float4*)&ht[wid][ 4 + lch4][lt8 * 4] = nh1;
        *(float4*)&ht[wid][ 8 + lch4][lt8 * 4] = nh2;
        *(float4*)&ht[wid][12 + lch4][lt8 * 4] = nh3;
        *(float4*)&ht[wid][16 + lch4][lt8 * 4] = nh4;
        *(float4*)&ht[wid][20 + lch4][lt8 * 4] = nh5;
        *(float4*)&ht[wid][24 + lch4][lt8 * 4] = nh6;
        *(float4*)&ht[wid][28 + lch4][lt8 * 4] = nh7;
        __syncwarp();

        if (tile + 1 < K1NT) { K1_LDALL((tile + 1) * 8) }

        // 32 steps for chain = lane; quantize g*karg with 1-way error feedback
        unsigned uq0 = 0, uq1 = 0;
        #pragma unroll
        for (int j = 0; j < 8; j++) {
            float4 fv = *(const float4*)&ft[wid][lane][4 * j];
            float4 hv = *(const float4*)&ht[wid][lane][4 * j];
            __half q0, q1, q2, q3;
            float g, t, r, acc;

            g = fmaf(ki, hv.x, fv.x); t = fmaf(g, karg, e);
            q0 = __float2half_rn(t);  r = __half2float(q0); e = t - r;
            acc = fmaf(nki, pos, r); vs = fmaf(vs, DAMP, acc); pos = fmaf(vs, DAMP, pos);

            g = fmaf(ki, hv.y, fv.y); t = fmaf(g, karg, e);
            q1 = __float2half_rn(t);  r = __half2float(q1); e = t - r;
            acc = fmaf(nki, pos, r); vs = fmaf(vs, DAMP, acc); pos = fmaf(vs, DAMP, pos);

            g = fmaf(ki, hv.z, fv.z); t = fmaf(g, karg, e);
            q2 = __float2half_rn(t);  r = __half2float(q2); e = t - r;
            acc = fmaf(nki, pos, r); vs = fmaf(vs, DAMP, acc); pos = fmaf(vs, DAMP, pos);

            g = fmaf(ki, hv.w, fv.w); t = fmaf(g, karg, e);
            q3 = __float2half_rn(t);  r = __half2float(q3); e = t - r;
            acc = fmaf(nki, pos, r); vs = fmaf(vs, DAMP, acc); pos = fmaf(vs, DAMP, pos);

            unsigned ua = half2_as_u32(__halves2half2(q0, q1));  // q0 low
            unsigned ub = half2_as_u32(__halves2half2(q2, q3));
            if ((j & 1) == 0) { uq0 = ua; uq1 = ub; }
            else {
                uint4 pk; pk.x = uq0; pk.y = uq1; pk.z = ua; pk.w = ub;
                __stcs(gw + (size_t)(tile * 4 + (j >> 1)) * 64, pk);
            }
        }
    }
#undef K1_LDALL

    float* fin = g_fin + ((size_t)(bm * NCH + chunk) * 64 + d) * 2;
    fin[0] = pos; fin[1] = vs;
}

// ---------------- K2: combine (inline homogeneous + chunk ICs) ----------------
__global__ __launch_bounds__(256)
void k2_combine(const float* __restrict__ masses, const float* __restrict__ tensions)
{
    int idx = blockIdx.x * 256 + threadIdx.x;      // bm*64+d
    int bm = idx >> 6, d = idx & 63, m = bm & 63;
    const float nki = -(tensions[m * 64 + d] / masses[m]);

    // homogeneous M^CL columns (two independent chains)
    float p1 = 1.f, v1 = 0.f, p2 = 0.f, v2 = 1.f;
    #pragma unroll 8
    for (int t = 0; t < CL; t++) {
        v1 = fmaf(v1, DAMP, nki * p1); p1 = fmaf(v1, DAMP, p1);
        v2 = fmaf(v2, DAMP, nki * p2); p2 = fmaf(v2, DAMP, p2);
    }

    float pos = 0.f, vs = 0.f;
    #pragma unroll
    for (int c = 0; c < NCH; c++) {
        size_t o = ((size_t)(bm * NCH + c) * 64 + d) * 2;
        g_ic[o] = pos; g_ic[o + 1] = vs;
        float np = fmaf(p1, pos, fmaf(p2, vs, g_fin[o]));
        float nv = fmaf(v1, pos, fmaf(v2, vs, g_fin[o + 1]));
        pos = np; vs = nv;
    }
}

// ---------------- K3: pass B — one warp per (bm,chunk), 2 chains per lane ----
__global__ __launch_bounds__(256)
void k3_passB(const float* __restrict__ mic, const float* __restrict__ masses,
              const float* __restrict__ tensions, float* __restrict__ out)
{
    __shared__ float tile_s[8][16][36];

    const int tid = threadIdx.x, wid = tid >> 5, lane = tid & 31;
    const int unit  = blockIdx.x * 8 + wid;        // 0..2047
    const int bm    = unit >> 4;
    const int chunk = unit & 15;
    const int m = bm & 63;
    const int d0 = lane, d1 = lane + 32;

    const float inv_mass = 1.f / masses[m];
    const float nki0 = -(tensions[m * 64 + d0] * inv_mass);
    const float nki1 = -(tensions[m * 64 + d1] * inv_mass);
    const float micv0 = mic[bm * 64 + d0];
    const float micv1 = mic[bm * 64 + d1];
    const float m2mic0 = -2.f * micv0;
    const float m2mic1 = -2.f * micv1;
    const float micsum = micv0 + micv1;

    const uint4* gw0 = g_scr + ((size_t)(bm * NCH + chunk) * NW8) * 64 + d0;
    const uint4* gw1 = gw0 + 32;
    const size_t ib = ((size_t)(bm * NCH + chunk) * 64) * 2;
    float pos0 = g_ic[ib + 2 * d0], vs0 = g_ic[ib + 2 * d0 + 1];
    float pos1 = g_ic[ib + 2 * d1], vs1 = g_ic[ib + 2 * d1 + 1];
    float* obase = out + (size_t)bm * TTX + (size_t)chunk * CL;
    float (*tile)[36] = tile_s[wid];

    uint4 ca00, ca01, ca10, ca11, cb00, cb01, cb10, cb11;
    ca00 = __ldcs(gw0 + 0);  ca01 = __ldcs(gw0 + 64);
    ca10 = __ldcs(gw1 + 0);  ca11 = __ldcs(gw1 + 64);

    const int NWND = CL / 16;                      // 32 windows of 16 steps

    // one uint4 pair (8 steps for both chains) starting at tile row R
#define K3_QQ(G0, G1, R)                                                       \
    _Pragma("unroll")                                                          \
    for (int i = 0; i < 4; i++) {                                              \
        float2 fa = __half22float2(u32_as_half2((&G0.x)[i]));                  \
        float2 fb = __half22float2(u32_as_half2((&G1.x)[i]));                  \
        _Pragma("unroll")                                                      \
        for (int s = 0; s < 2; s++) {                                          \
            float gv0 = s ? fa.y : fa.x;                                       \
            float gv1 = s ? fb.y : fb.x;                                       \
            float a0 = fmaf(nki0, pos0, gv0);                                  \
            vs0  = fmaf(vs0, DAMP, a0);                                        \
            pos0 = fmaf(vs0, DAMP, pos0);                                      \
            float a1 = fmaf(nki1, pos1, gv1);                                  \
            vs1  = fmaf(vs1, DAMP, a1);                                        \
            pos1 = fmaf(vs1, DAMP, pos1);                                      \
            float r0 = rcp_fast(ex2_fast(vs0) + 1.f);                          \
            float r1 = rcp_fast(ex2_fast(vs1) + 1.f);                          \
            tile[(R) + i * 2 + s][lane] =                                      \
                fmaf(r0, m2mic0, fmaf(r1, m2mic1, micsum));                    \
        }                                                                      \
    }

#define K3W(W, C00, C01, C10, C11, N00, N01, N10, N11)                         \
    {                                                                          \
        const int w_ = (W);                                                    \
        if (w_ + 1 < NWND) {                                                   \
            N00 = __ldcs(gw0 + (size_t)(2 * (w_ + 1) + 0) * 64);               \
            N01 = __ldcs(gw0 + (size_t)(2 * (w_ + 1) + 1) * 64);               \
            N10 = __ldcs(gw1 + (size_t)(2 * (w_ + 1) + 0) * 64);               \
            N11 = __ldcs(gw1 + (size_t)(2 * (w_ + 1) + 1) * 64);               \
        }                                                                      \
        K3_QQ(C00, C10, 0)                                                     \
        K3_QQ(C01, C11, 8)                                                     \
        __syncwarp();                                                          \
        const int row = lane & 15, cb = (lane >> 4) * 16;                      \
        float s0 = 0.f, s1 = 0.f, s2 = 0.f, s3 = 0.f;                          \
        _Pragma("unroll")                                                      \
        for (int i = 0; i < 4; i++) {                                          \
            float4 v = *(const float4*)&tile[row][cb + 4 * i];                 \
            s0 += v.x; s1 += v.y; s2 += v.z; s3 += v.w;                        \
        }                                                                      \
        float sum = (s0 + s1) + (s2 + s3);                                     \
        sum += __shfl_down_sync(0xffffffffu, sum, 16);                         \
        if (lane < 16) obase[w_ * 16 + lane] = sum;                            \
        __syncwarp();                                                          \
    }

    for (int w = 0; w < NWND; w += 2) {
        K3W(w,     ca00, ca01, ca10, ca11, cb00, cb01, cb10, cb11)
        K3W(w + 1, cb00, cb01, cb10, cb11, ca00, ca01, ca10, ca11)
    }
#undef K3W
#undef K3_QQ
}

extern "C" void kernel_launch(void* const* d_in, const int* in_sizes, int n_in,
                              void* d_out, int out_size)
{
    const float* forces   = (const float*)d_in[0];
    const float* home     = (const float*)d_in[1];
    const float* mic      = (const float*)d_in[2];
    const float* masses   = (const float*)d_in[3];
    const float* tensions = (const float*)d_in[4];
    const float* gains    = (const float*)d_in[5];

    k1_passA  <<<1024, 128>>>(forces, home, masses, tensions, gains);
    k2_combine<<<32,   256>>>(masses, tensions);
    k3_passB  <<<256,  256>>>(mic, masses, tensions, (float*)d_out);
}